// round 15
// baseline (speedup 1.0000x reference)
#include <cuda_runtime.h>
#include <cuda_bf16.h>
#include <stdint.h>

#define BB  4
#define CC  512
#define LL  1024
#define HH  8
#define DD  64
#define FCC 2048
#define NLL 4
#define WW  4
#define EPSC 1e-6f
#define SCALEC 0.125f   // 64^-0.5

// ---------------- scratch (static device memory; no allocations) ----------------
__device__ float g_x[BB*CC*LL];     // residual stream, full fp32
__device__ float g_xr[BB*CC*LL];    // tf32-rounded mirror of residual (GEMM operand)
__device__ float g_q[BB*CC*LL];
__device__ float g_k[BB*CC*LL];     // K bf16 (half used); reused as split-K partial #2
__device__ float g_v[BB*CC*LL];     // V bf16 (half used)
__device__ float g_a[BB*CC*LL];
__device__ float g_t[BB*CC*LL];
__device__ float g_h[(size_t)BB*FCC*LL];
__device__ float g_zero[CC];        // zero-initialized (bias for split-K part 1)
__device__ float g_mb[BB*LL];       // additive mask bias: 0 or -1e4
// tf32-rounded weight mirrors
__device__ float g_rwq[NLL*CC*CC];
__device__ float g_rwk[NLL*CC*CC];
__device__ float g_rwv[NLL*CC*CC];
__device__ float g_rwo[NLL*CC*CC];
__device__ float g_rw1[(size_t)NLL*FCC*CC];
__device__ float g_rw2[(size_t)NLL*FCC*CC];

// ---------------- helpers --------------------------------------------------------
__device__ __forceinline__ uint32_t f2tf(float x) {
    uint32_t t;
    asm volatile("cvt.rna.tf32.f32 %0, %1;" : "=r"(t) : "f"(x));
    return t;
}
__device__ __forceinline__ float rntf(float x) { return __uint_as_float(f2tf(x)); }

__device__ __forceinline__ uint32_t packbf2(float lo, float hi) {
    __nv_bfloat162 h = __floats2bfloat162_rn(lo, hi);
    return *(uint32_t*)&h;
}

__device__ __forceinline__ void mma_tf32(float* c, const uint32_t* a, const uint32_t* b) {
    asm volatile(
        "mma.sync.aligned.m16n8k8.row.col.f32.tf32.tf32.f32 "
        "{%0,%1,%2,%3}, {%4,%5,%6,%7}, {%8,%9}, {%0,%1,%2,%3};\n"
        : "+f"(c[0]), "+f"(c[1]), "+f"(c[2]), "+f"(c[3])
        : "r"(a[0]), "r"(a[1]), "r"(a[2]), "r"(a[3]), "r"(b[0]), "r"(b[1]));
}

__device__ __forceinline__ void mma_bf16(float* c, const uint32_t* a, const uint32_t* b) {
    asm volatile(
        "mma.sync.aligned.m16n8k16.row.col.f32.bf16.bf16.f32 "
        "{%0,%1,%2,%3}, {%4,%5,%6,%7}, {%8,%9}, {%0,%1,%2,%3};\n"
        : "+f"(c[0]), "+f"(c[1]), "+f"(c[2]), "+f"(c[3])
        : "r"(a[0]), "r"(a[1]), "r"(a[2]), "r"(a[3]), "r"(b[0]), "r"(b[1]));
}

__device__ __forceinline__ void cpa16(uint32_t s, const void* g) {
    asm volatile("cp.async.cg.shared.global [%0], [%1], 16;" :: "r"(s), "l"(g));
}

__device__ __forceinline__ void ldm_x4(uint32_t* r, uint32_t a) {
    asm volatile("ldmatrix.sync.aligned.m8n8.x4.shared.b16 {%0,%1,%2,%3}, [%4];"
        : "=r"(r[0]), "=r"(r[1]), "=r"(r[2]), "=r"(r[3]) : "r"(a));
}

__device__ __forceinline__ void ldm_x4_t(uint32_t* r, uint32_t a) {
    asm volatile("ldmatrix.sync.aligned.m8n8.x4.trans.shared.b16 {%0,%1,%2,%3}, [%4];"
        : "=r"(r[0]), "=r"(r[1]), "=r"(r[2]), "=r"(r[3]) : "r"(a));
}

// ---------------- prep: ALL weight mirrors in ONE launch -------------------------
#define NW4 (NLL*CC*CC/4)
#define NF4 ((size_t)NLL*FCC*CC/4)
__global__ void roundcpy6_kernel(
    const float4* __restrict__ a0, const float4* __restrict__ a1,
    const float4* __restrict__ a2, const float4* __restrict__ a3,
    const float4* __restrict__ a4, const float4* __restrict__ a5,
    float4* __restrict__ y0, float4* __restrict__ y1, float4* __restrict__ y2,
    float4* __restrict__ y3, float4* __restrict__ y4, float4* __restrict__ y5)
{
    size_t i = (size_t)blockIdx.x * 256 + threadIdx.x;
    const float4* src; float4* dst; size_t off;
    if (i < (size_t)4 * NW4) {
        int w = (int)(i / NW4); off = i % NW4;
        src = (w == 0) ? a0 : (w == 1) ? a1 : (w == 2) ? a2 : a3;
        dst = (w == 0) ? y0 : (w == 1) ? y1 : (w == 2) ? y2 : y3;
    } else {
        size_t j = i - (size_t)4 * NW4;
        int w = (int)(j / NF4); off = j % NF4;
        src = (w == 0) ? a4 : a5;
        dst = (w == 0) ? y4 : y5;
    }
    float4 v = src[off];
    v.x = rntf(v.x); v.y = rntf(v.y); v.z = rntf(v.z); v.w = rntf(v.w);
    dst[off] = v;
}

// ---------------- elementwise: px/pxr + mask bias (fused) ------------------------
__global__ void maskmul_kernel(const float* __restrict__ X, const float* __restrict__ msk,
                               float* __restrict__ Y, float* __restrict__ Yr,
                               float* __restrict__ mb) {
    int i = blockIdx.x * 256 + threadIdx.x;
    int l = i & (LL - 1);
    int bc = i / LL;
    int b = bc / CC;
    float m = msk[b * LL + l];
    float v = X[i] * m;
    Y[i] = v;
    Yr[i] = rntf(v);
    if ((bc & (CC - 1)) == 0) mb[b * LL + l] = (m == 0.f) ? -1e4f : 0.f;
}

// ---------------- tf32 tensor-core GEMM v8: k-step 32, 3-stage, 1 bar/32k --------
#define APAD 36
#define BPAD 136
#define STG_A (128 * APAD)       // 4608 floats
#define STG_B (32 * BPAD)        // 4352 floats
#define NSTG 3
__global__ __launch_bounds__(256, 2) void gemm_tc_kernel(
    const float* __restrict__ W0, const float* __restrict__ W1p, const float* __restrict__ W2p,
    const float* __restrict__ c0, const float* __restrict__ c1, const float* __restrict__ c2,
    const float* __restrict__ X, const float* __restrict__ msk,
    float* __restrict__ Y0, float* __restrict__ Y1p, float* __restrict__ Y2p,
    int M, int N, int K, int flags)
{
    extern __shared__ float gsm[];
    float* As = gsm;
    float* Bs = gsm + NSTG * STG_A;

    const int tid  = threadIdx.x;
    const int mat  = blockIdx.z / BB;
    const int b    = blockIdx.z % BB;
    const bool splitk = flags & 8;
    const float* Wm   = (mat == 0) ? W0 : (mat == 1 ? W1p : W2p);
    const float* bias = (mat == 0) ? c0 : (mat == 1 ? c1 : c2);
    float*       Y    = (mat == 0) ? Y0 : (mat == 1 ? Y1p : Y2p);

    const int Keff = splitk ? (K >> 1) : K;
    const int kOff = splitk ? mat * Keff : 0;

    const int bm = blockIdx.y * 128, bn = blockIdx.x * 128;
    const float* mp = msk + (size_t)b * LL;

    const float* Ag = Wm + (size_t)bm * K + kOff;
    const float* Bg = X + (size_t)b * K * N + (size_t)kOff * N + bn;

    // staging maps: A 128x32 (4 chunks/thr), B 32x128 (4 chunks/thr)
    const int arow = tid >> 3;            // +32 per chunk
    const int akq  = (tid & 7) * 4;
    const int bkr  = tid >> 5;            // +8 per chunk
    const int bn4  = (tid & 31) * 4;

    const uint32_t sA = (uint32_t)__cvta_generic_to_shared(As);
    const uint32_t sB = (uint32_t)__cvta_generic_to_shared(Bs);

    #define ISSUE(ST, K0) do { \
        _Pragma("unroll") \
        for (int c = 0; c < 4; c++) { \
            int r_ = arow + c * 32; \
            cpa16(sA + (uint32_t)(((ST) * STG_A) + r_ * APAD + akq) * 4, \
                  Ag + (size_t)r_ * K + (K0) + akq); \
        } \
        _Pragma("unroll") \
        for (int c = 0; c < 4; c++) { \
            int kr = bkr + c * 8; \
            cpa16(sB + (uint32_t)(((ST) * STG_B) + kr * BPAD + bn4) * 4, \
                  Bg + (size_t)((K0) + kr) * N + bn4); \
        } \
        asm volatile("cp.async.commit_group;" ::: "memory"); \
    } while (0)

    const int lane = tid & 31, warp = tid >> 5;
    const int wm = (warp >> 2) * 64;
    const int wn = (warp & 3) * 32;
    const int lm = lane >> 2, lk = lane & 3;
    const int mrow = (lane & 7) + ((lane >> 3) & 1) * 8;
    const int kadd = (lane >> 4) * 4;

    float acc[4][4][4];
    #pragma unroll
    for (int i = 0; i < 4; i++)
        #pragma unroll
        for (int j = 0; j < 4; j++)
            #pragma unroll
            for (int r = 0; r < 4; r++) acc[i][j][r] = 0.f;

    const int nIter = Keff / 32;     // 8, 16, or 16
    ISSUE(0, 0);
    ISSUE(1, 32);

    for (int it = 0; it < nIter; it++) {
        asm volatile("cp.async.wait_group 1;" ::: "memory");
        __syncthreads();
        if (it + 2 < nIter) ISSUE((it + 2) % 3, (it + 2) * 32);
        else asm volatile("cp.async.commit_group;" ::: "memory");

        const int buf = it % 3;
        const uint32_t aBase = sA + (uint32_t)(buf * STG_A) * 4;
        const float* Bb = Bs + buf * STG_B;
        #pragma unroll
        for (int ks = 0; ks < 32; ks += 8) {
            uint32_t a[4][4], bfr[4][2];
            #pragma unroll
            for (int mt = 0; mt < 4; mt++)
                ldm_x4(a[mt], aBase + (uint32_t)((wm + mt*16 + mrow) * APAD + ks + kadd) * 4);
            #pragma unroll
            for (int nt = 0; nt < 4; nt++) {
                bfr[nt][0] = __float_as_uint(Bb[(ks + lk    ) * BPAD + wn + nt*8 + lm]);
                bfr[nt][1] = __float_as_uint(Bb[(ks + lk + 4) * BPAD + wn + nt*8 + lm]);
            }
            #pragma unroll
            for (int mt = 0; mt < 4; mt++)
                #pragma unroll
                for (int nt = 0; nt < 4; nt++)
                    mma_tf32(acc[mt][nt], a[mt], bfr[nt]);
        }
    }
    #undef ISSUE

    const bool relu = flags & 2;
    const bool omask = flags & 4;
    const bool rnd = flags & 16;
    const bool h16 = (flags & 32) && (mat >= 1);
    float* Yb = Y + (size_t)b * M * N;
    __nv_bfloat16* Yh = (__nv_bfloat16*)Y + (size_t)b * M * N;
    #pragma unroll
    for (int mt = 0; mt < 4; mt++) {
        #pragma unroll
        for (int half = 0; half < 2; half++) {
            int m = bm + wm + mt * 16 + lm + half * 8;
            float bv = bias[m];
            #pragma unroll
            for (int nt = 0; nt < 4; nt++) {
                int n = bn + wn + nt * 8 + lk * 2;
                float v0 = acc[mt][nt][half * 2 + 0] + bv;
                float v1 = acc[mt][nt][half * 2 + 1] + bv;
                if (relu) { v0 = fmaxf(v0, 0.f); v1 = fmaxf(v1, 0.f); }
                if (omask) { v0 *= mp[n]; v1 *= mp[n + 1]; }
                if (h16) {
                    *(__nv_bfloat162*)&Yh[(size_t)m * N + n] = __floats2bfloat162_rn(v0, v1);
                } else {
                    if (rnd) { v0 = rntf(v0); v1 = rntf(v1); }
                    *(float2*)&Yb[(size_t)m * N + n] = make_float2(v0, v1);
                }
            }
        }
    }
}

// ---------------- tensor-core flash attention v9 (unchanged from R14) ------------
#define KSTRH 72                  // bf16 units (144B pitch)
#define KTILEH (64 * KSTRH)
#define VSTRH 72
#define VTILEH (64 * VSTRH)
__global__ __launch_bounds__(256, 2) void attn_tc_kernel(
    const float* __restrict__ Q, const __nv_bfloat16* __restrict__ Kk,
    const __nv_bfloat16* __restrict__ V, const float* __restrict__ mbias,
    const float* __restrict__ relk, const float* __restrict__ relv,
    float* __restrict__ O)
{
    extern __shared__ float smem[];
    float* qs = smem;                                     // [128][73] fp32
    __nv_bfloat16* ksh = (__nv_bfloat16*)(qs + 128 * 73); // 3 x [64][72] bf16
    __nv_bfloat16* vsh = ksh + 3 * KTILEH;                // 3 x [64][72] bf16
    float* rks   = (float*)(vsh + 3 * VTILEH);            // [9][64]
    float* rvs   = rks   + 9 * 64;                        // [9][64]
    float* relb  = rvs   + 9 * 64;                        // [128][12]
    float* pwin  = relb  + 128 * 12;                      // [128][12]
    float* invli = pwin  + 128 * 12;                      // [128]
    float* msksb = invli + 128;                           // 3 x [64] additive bias

    const int tid = threadIdx.x;
    const int lane = tid & 31, warp = tid >> 5;
    const int b = blockIdx.z, h = blockIdx.y;
    const int l0 = blockIdx.x * 128;

    const float* qp = Q  + ((size_t)b * CC + h * DD) * LL;
    const __nv_bfloat16* kph = Kk + ((size_t)b * CC + h * DD) * LL;
    const __nv_bfloat16* vph = V + ((size_t)b * CC + h * DD) * LL;
    const float* mbp = mbias + (size_t)b * LL;

    const uint32_t sK = (uint32_t)__cvta_generic_to_shared(ksh);
    const uint32_t sV = (uint32_t)__cvta_generic_to_shared(vsh);
    const uint32_t sM = (uint32_t)__cvta_generic_to_shared(msksb);

    #define AISSUE(ST, T) do { \
        const int _m0 = (T) * 64; \
        _Pragma("unroll") \
        for (int i = 0; i < 2; i++) { \
            int ch = i * 256 + tid; \
            int vd = ch >> 3, vm = (ch & 7) * 8; \
            cpa16(sK + (uint32_t)((ST) * KTILEH + vd * KSTRH + vm) * 2, \
                  kph + (size_t)vd * LL + _m0 + vm); \
            cpa16(sV + (uint32_t)((ST) * VTILEH + vd * VSTRH + vm) * 2, \
                  vph + (size_t)vd * LL + _m0 + vm); \
        } \
        if (tid < 16) cpa16(sM + (uint32_t)((ST) * 64 + tid * 4) * 4, mbp + _m0 + tid * 4); \
        asm volatile("cp.async.commit_group;" ::: "memory"); \
    } while (0)

    AISSUE(0, 0);
    AISSUE(1, 1);

    #pragma unroll
    for (int i = 0; i < 8; i++) {
        int d = (tid >> 5) + i * 8;
        int l = (tid & 31) * 4;
        float4 qv = *(const float4*)&qp[(size_t)d * LL + l0 + l];
        qs[(l+0)*73 + d] = qv.x * SCALEC;
        qs[(l+1)*73 + d] = qv.y * SCALEC;
        qs[(l+2)*73 + d] = qv.z * SCALEC;
        qs[(l+3)*73 + d] = qv.w * SCALEC;
    }
    for (int i = tid; i < 9 * 64; i += 256) { rks[i] = relk[i]; rvs[i] = relv[i]; }
    for (int i = tid; i < 128 * 12; i += 256) pwin[i] = 0.f;
    __syncthreads();

    for (int i = tid; i < 128 * 9; i += 256) {
        int l = i / 9, df = i % 9;
        const float* qq = &qs[l * 73];
        const float* rr = &rks[df * 64];
        float a = 0.f;
        #pragma unroll 16
        for (int d = 0; d < DD; d++) a = fmaf(qq[d], rr[d], a);
        relb[l * 12 + df] = a;
    }

    const int r0 = warp * 16 + (lane >> 2);
    const int r1 = r0 + 8;
    const int lk = lane & 3, lm = lane >> 2;

    uint32_t qf[4][4];
    #pragma unroll
    for (int c = 0; c < 4; c++) {
        int kb = c * 16 + 2 * lk;
        qf[c][0] = packbf2(qs[r0*73 + kb    ], qs[r0*73 + kb + 1]);
        qf[c][1] = packbf2(qs[r1*73 + kb    ], qs[r1*73 + kb + 1]);
        qf[c][2] = packbf2(qs[r0*73 + kb + 8], qs[r0*73 + kb + 9]);
        qf[c][3] = packbf2(qs[r1*73 + kb + 8], qs[r1*73 + kb + 9]);
    }

    const uint32_t vBrowBase = (uint32_t)(((lane >> 4) & 1) * 8 + (lane & 7));
    const uint32_t vBcol = (uint32_t)(((lane >> 3) & 1) * 16);
    const uint32_t kBrow = (uint32_t)(((lane >> 3) & 1) * 8 + (lane & 7));
    const uint32_t kBnb  = (uint32_t)(((lane >> 4) & 1) * 8);

    float co[8][4];
    #pragma unroll
    for (int nt = 0; nt < 8; nt++)
        #pragma unroll
        for (int j = 0; j < 4; j++) co[nt][j] = 0.f;
    float li0 = 0.f, li1 = 0.f;

    const int wrow = l0 + warp * 16;

    const int NT = LL / 64;
    for (int t = 0; t < NT; t++) {
        const int m0 = t * 64;
        asm volatile("cp.async.wait_group 1;" ::: "memory");
        __syncthreads();
        if (t + 2 < NT) AISSUE((t + 2) % 3, t + 2);
        else asm volatile("cp.async.commit_group;" ::: "memory");

        const int buf = t % 3;
        const uint32_t kbase = sK + (uint32_t)(buf * KTILEH) * 2;
        const uint32_t vbase = sV + (uint32_t)(buf * VTILEH) * 2;
        const float* msks = msksb + buf * 64;

        const bool haswin = (m0 + 63 >= wrow - WW) && (m0 <= wrow + 15 + WW);

        float s[8][4];
        #pragma unroll
        for (int nt = 0; nt < 8; nt++)
            #pragma unroll
            for (int j = 0; j < 4; j++) s[nt][j] = 0.f;

        #pragma unroll
        for (int kk2 = 0; kk2 < 4; kk2++) {
            #pragma unroll
            for (int ntp = 0; ntp < 4; ntp++) {
                uint32_t bk[4];
                ldm_x4_t(bk, kbase + ((uint32_t)(kk2*16) + kBrow) * (KSTRH*2)
                             + ((uint32_t)(ntp*16) + kBnb) * 2);
                mma_bf16(s[2*ntp    ], qf[kk2], bk);
                mma_bf16(s[2*ntp + 1], qf[kk2], bk + 2);
            }
        }

        const int gl0 = l0 + r0, gl1 = l0 + r1;
        if (haswin) {
            #pragma unroll
            for (int nt = 0; nt < 8; nt++) {
                #pragma unroll
                for (int j = 0; j < 2; j++) {
                    int gm = m0 + nt*8 + 2*lk + j;
                    int df0 = gm - gl0;
                    if (df0 >= -WW && df0 <= WW) s[nt][j] += relb[r0*12 + df0 + WW];
                    int df1 = gm - gl1;
                    if (df1 >= -WW && df1 <= WW) s[nt][2+j] += relb[r1*12 + df1 + WW];
                }
            }
        }
        #pragma unroll
        for (int nt = 0; nt < 8; nt++) {
            #pragma unroll
            for (int j = 0; j < 2; j++) {
                float mb = msks[nt*8 + 2*lk + j];
                s[nt][j] += mb;
                s[nt][2+j] += mb;
            }
        }

        #pragma unroll
        for (int nt = 0; nt < 8; nt++) {
            s[nt][0] = __expf(s[nt][0]); s[nt][1] = __expf(s[nt][1]);
            s[nt][2] = __expf(s[nt][2]); s[nt][3] = __expf(s[nt][3]);
            li0 += s[nt][0] + s[nt][1];
            li1 += s[nt][2] + s[nt][3];
        }

        if (haswin) {
            #pragma unroll
            for (int nt = 0; nt < 8; nt++) {
                #pragma unroll
                for (int j = 0; j < 2; j++) {
                    int gm = m0 + nt*8 + 2*lk + j;
                    int df0 = gm - gl0;
                    if (df0 >= -WW && df0 <= WW) pwin[r0*12 + df0 + WW] = s[nt][j];
                    int df1 = gm - gl1;
                    if (df1 >= -WW && df1 <= WW) pwin[r1*12 + df1 + WW] = s[nt][2+j];
                }
            }
        }

        #pragma unroll
        for (int kk2 = 0; kk2 < 4; kk2++) {
            uint32_t a[4];
            a[0] = packbf2(s[2*kk2  ][0], s[2*kk2  ][1]);
            a[1] = packbf2(s[2*kk2  ][2], s[2*kk2  ][3]);
            a[2] = packbf2(s[2*kk2+1][0], s[2*kk2+1][1]);
            a[3] = packbf2(s[2*kk2+1][2], s[2*kk2+1][3]);
            #pragma unroll
            for (int ntp = 0; ntp < 4; ntp++) {
                uint32_t bv[4];
                uint32_t vrow = (uint32_t)(2*ntp*8) + vBrowBase;
                ldm_x4(bv, vbase + vrow * (VSTRH*2) + (uint32_t)(kk2*32) + vBcol);
                mma_bf16(co[2*ntp    ], a, bv);
                mma_bf16(co[2*ntp + 1], a, bv + 2);
            }
        }
    }
    #undef AISSUE

    li0 += __shfl_xor_sync(0xffffffffu, li0, 1);
    li0 += __shfl_xor_sync(0xffffffffu, li0, 2);
    li1 += __shfl_xor_sync(0xffffffffu, li1, 1);
    li1 += __shfl_xor_sync(0xffffffffu, li1, 2);

    __syncthreads();
    float* outb = (float*)ksh;
    float inv0 = 1.0f / fmaxf(li0, 1e-20f);
    float inv1 = 1.0f / fmaxf(li1, 1e-20f);
    if (lk == 0) { invli[r0] = inv0; invli[r1] = inv1; }
    #pragma unroll
    for (int nt = 0; nt < 8; nt++) {
        int c = nt*8 + 2*lk;
        outb[r0*73 + c    ] = co[nt][0] * inv0;
        outb[r0*73 + c + 1] = co[nt][1] * inv0;
        outb[r1*73 + c    ] = co[nt][2] * inv1;
        outb[r1*73 + c + 1] = co[nt][3] * inv1;
    }
    __syncthreads();

    float* op = O + ((size_t)b * CC + h * DD) * LL;
    #pragma unroll
    for (int i = 0; i < 32; i++) {
        int idx = i * 256 + tid;
        int l = idx & 127;
        int d = idx >> 7;
        float r = 0.f;
        #pragma unroll
        for (int df = 0; df < 9; df++) r = fmaf(pwin[l*12 + df], rvs[df*64 + d], r);
        op[(size_t)d * LL + l0 + l] = rntf(outb[l*73 + d] + invli[l] * r);
    }
}

// ---------- fused residual add (2 deltas) + LayerNorm, smem-cached ---------------
__global__ void add_ln_kernel(const float* __restrict__ X, const float* __restrict__ D0,
                              const float* __restrict__ D1,
                              const float* __restrict__ gam, const float* __restrict__ bet,
                              float* __restrict__ Yo, float* __restrict__ Yr,
                              float* __restrict__ Yext, const float* __restrict__ fm)
{
    __shared__ float vbuf[CC][17];
    __shared__ float sm[16][17], sq[16][17];
    int b = blockIdx.y;
    int l = blockIdx.x * 16 + threadIdx.x;
    int cg = threadIdx.y;
    int lx = threadIdx.x;
    const size_t base = (size_t)b * CC * LL + l;

    float s = 0.f, s2 = 0.f;
    for (int c = cg; c < CC; c += 16) {
        float v = X[base + (size_t)c * LL] + D0[base + (size_t)c * LL] + D1[base + (size_t)c * LL];
        vbuf[c][lx] = v;
        s += v; s2 += v * v;
    }
    sm[cg][lx] = s; sq[cg][lx] = s2;
    __syncthreads();
    float ts = 0.f, ts2 = 0.f;
    #pragma unroll
    for (int i = 0; i < 16; i++) { ts += sm[i][lx]; ts2 += sq[i][lx]; }
    float mean = ts * (1.0f / CC);
    float var  = ts2 * (1.0f / CC) - mean * mean;
    float rstd = rsqrtf(var + EPSC);
    float mval = Yext ? fm[(size_t)b * LL + l] : 0.f;
    for (int c = cg; c < CC; c += 16) {
        float v = vbuf[c][lx];
        float y = (v - mean) * rstd * gam[c] + bet[c];
        Yo[base + (size_t)c * LL] = y;
        Yr[base + (size_t)c * LL] = rntf(y);
        if (Yext) Yext[base + (size_t)c * LL] = y * mval;
    }
}

// ---------------- host orchestration -------------------------------------------
extern "C" void kernel_launch(void* const* d_in, const int* in_sizes, int n_in,
                              void* d_out, int out_size)
{
    const float* x    = (const float*)d_in[0];
    const float* mask = (const float*)d_in[1];
    const float* wq = (const float*)d_in[2];  const float* bq = (const float*)d_in[3];
    const float* wk = (const float*)d_in[4];  const float* bk = (const float*)d_in[5];
    const float* wv = (const float*)d_in[6];  const float* bv = (const float*)d_in[7];
    const float* wo = (const float*)d_in[8];  const float* bo = (const float*)d_in[9];
    const float* relk = (const float*)d_in[10];
    const float* relv = (const float*)d_in[11];
    const float* ln1g = (const float*)d_in[12]; const float* ln1b = (const float*)d_in[13];
    const float* w1 = (const float*)d_in[14]; const float* b1 = (const float*)d_in[15];
    const float* w2 = (const float*)d_in[16]; const float* b2 = (const float*)d_in[17];
    const float* ln2g = (const float*)d_in[18]; const float* ln2b = (const float*)d_in[19];

    float *px, *pxr, *pq, *pk, *pv, *pa, *pt, *ph, *pz, *pmb;
    float *rwq, *rwk, *rwv, *rwo, *rw1, *rw2;
    cudaGetSymbolAddress((void**)&px, g_x);
    cudaGetSymbolAddress((void**)&pxr, g_xr);
    cudaGetSymbolAddress((void**)&pq, g_q);
    cudaGetSymbolAddress((void**)&pk, g_k);
    cudaGetSymbolAddress((void**)&pv, g_v);
    cudaGetSymbolAddress((void**)&pa, g_a);
    cudaGetSymbolAddress((void**)&pt, g_t);
    cudaGetSymbolAddress((void**)&ph, g_h);
    cudaGetSymbolAddress((void**)&pz, g_zero);
    cudaGetSymbolAddress((void**)&pmb, g_mb);
    cudaGetSymbolAddress((void**)&rwq, g_rwq);
    cudaGetSymbolAddress((void**)&rwk, g_rwk);
    cudaGetSymbolAddress((void**)&rwv, g_rwv);
    cudaGetSymbolAddress((void**)&rwo, g_rwo);
    cudaGetSymbolAddress((void**)&rw1, g_rw1);
    cudaGetSymbolAddress((void**)&rw2, g_rw2);
    float* pt2 = pk;   // split-K partial #2

    const size_t attn_smem = (size_t)(128*73) * 4
                           + (size_t)(3*KTILEH + 3*VTILEH) * 2
                           + (size_t)(9*64*2 + 128*12*2 + 128 + 3*64) * 4;
    cudaFuncSetAttribute(attn_tc_kernel, cudaFuncAttributeMaxDynamicSharedMemorySize, (int)attn_smem);
    const size_t gemm_smem = (size_t)(NSTG * STG_A + NSTG * STG_B) * sizeof(float);
    cudaFuncSetAttribute(gemm_tc_kernel, cudaFuncAttributeMaxDynamicSharedMemorySize, (int)gemm_smem);

    const size_t totalF4 = (size_t)4 * NW4 + 2 * NF4;
    roundcpy6_kernel<<<(unsigned)(totalF4 / 256), 256>>>(
        (const float4*)wq, (const float4*)wk, (const float4*)wv, (const float4*)wo,
        (const float4*)w1, (const float4*)w2,
        (float4*)rwq, (float4*)rwk, (float4*)rwv, (float4*)rwo,
        (float4*)rw1, (float4*)rw2);

    const int nElem = BB * CC * LL;
    maskmul_kernel<<<nElem / 256, 256>>>(x, mask, px, pxr, pmb);

    dim3 gQKV(LL / 128, CC / 128, 3 * BB);
    dim3 gSK(LL / 128, CC / 128, 2 * BB);
    dim3 gF1(LL / 128, FCC / 128, BB);
    dim3 gAttn(LL / 128, HH, BB);
    dim3 gLN(LL / 16, BB);
    dim3 bLN(16, 16);

    for (int i = 0; i < NLL; i++) {
        const float* Wq = rwq + (size_t)i * CC * CC;
        const float* Wk = rwk + (size_t)i * CC * CC;
        const float* Wv = rwv + (size_t)i * CC * CC;
        const float* Wo = rwo + (size_t)i * CC * CC;
        const float* W1 = rw1 + (size_t)i * FCC * CC;
        const float* W2 = rw2 + (size_t)i * CC * FCC;
        const bool last = (i == NLL - 1);

        gemm_tc_kernel<<<gQKV, 256, gemm_smem>>>(Wq, Wk, Wv, bq + i*CC, bk + i*CC, bv + i*CC,
                                                 pxr, mask, pq, pk, pv, CC, LL, CC, 16 | 32);

        attn_tc_kernel<<<gAttn, 256, attn_smem>>>(pq, (const __nv_bfloat16*)pk,
                                                  (const __nv_bfloat16*)pv, pmb,
                                                  relk + (size_t)i * 9 * DD,
                                                  relv + (size_t)i * 9 * DD, pa);

        gemm_tc_kernel<<<gSK, 256, gemm_smem>>>(Wo, Wo, Wo, bo + i*CC, pz, pz,
                                                pa, mask, pt, pt2, pt2, CC, LL, CC, 8);
        add_ln_kernel<<<gLN, bLN>>>(px, pt, pt2, ln1g + i*CC, ln1b + i*CC,
                                    px, pxr, nullptr, mask);

        gemm_tc_kernel<<<gF1, 256, gemm_smem>>>(W1, W1, W1, b1 + i*FCC, b1 + i*FCC, b1 + i*FCC,
                                                pxr, mask, ph, ph, ph, FCC, LL, CC, 2 | 4 | 16);
        gemm_tc_kernel<<<gSK, 256, gemm_smem>>>(W2, W2, W2, b2 + i*CC, pz, pz,
                                                ph, mask, pt, pt2, pt2, CC, LL, FCC, 8 | 4);
        add_ln_kernel<<<gLN, bLN>>>(px, pt, pt2, ln2g + i*CC, ln2b + i*CC,
                                    px, pxr, last ? (float*)d_out : nullptr, mask);
    }
}

// round 16
// speedup vs baseline: 1.4721x; 1.4721x over previous
#include <cuda_runtime.h>
#include <cuda_bf16.h>
#include <stdint.h>

#define BB  4
#define CC  512
#define LL  1024
#define HH  8
#define DD  64
#define FCC 2048
#define NLL 4
#define WW  4
#define EPSC 1e-6f
#define SCALEC 0.125f   // 64^-0.5

// ---------------- scratch (static device memory; no allocations) ----------------
__device__ float g_x[BB*CC*LL];     // residual stream, full fp32
__device__ float g_xr[BB*CC*LL];    // tf32-rounded mirror of residual (GEMM operand)
__device__ float g_q[BB*CC*LL];
__device__ float g_k[BB*CC*LL];     // K bf16 (half used); reused as split-K partial #2
__device__ float g_v[BB*CC*LL];     // V bf16 (half used)
__device__ float g_a[BB*CC*LL];
__device__ float g_t[BB*CC*LL];
__device__ float g_h[(size_t)BB*FCC*LL];
__device__ float g_zero[CC];        // zero-initialized (bias for split-K part 1)
__device__ float g_mb[BB*LL];       // additive mask bias: 0 or -1e4
// tf32-rounded weight mirrors
__device__ float g_rwq[NLL*CC*CC];
__device__ float g_rwk[NLL*CC*CC];
__device__ float g_rwv[NLL*CC*CC];
__device__ float g_rwo[NLL*CC*CC];
__device__ float g_rw1[(size_t)NLL*FCC*CC];
__device__ float g_rw2[(size_t)NLL*FCC*CC];

// ---------------- helpers --------------------------------------------------------
__device__ __forceinline__ uint32_t f2tf(float x) {
    uint32_t t;
    asm volatile("cvt.rna.tf32.f32 %0, %1;" : "=r"(t) : "f"(x));
    return t;
}
__device__ __forceinline__ float rntf(float x) { return __uint_as_float(f2tf(x)); }

__device__ __forceinline__ uint32_t packbf2(float lo, float hi) {
    __nv_bfloat162 h = __floats2bfloat162_rn(lo, hi);
    return *(uint32_t*)&h;
}

__device__ __forceinline__ void mma_tf32(float* c, const uint32_t* a, const uint32_t* b) {
    asm volatile(
        "mma.sync.aligned.m16n8k8.row.col.f32.tf32.tf32.f32 "
        "{%0,%1,%2,%3}, {%4,%5,%6,%7}, {%8,%9}, {%0,%1,%2,%3};\n"
        : "+f"(c[0]), "+f"(c[1]), "+f"(c[2]), "+f"(c[3])
        : "r"(a[0]), "r"(a[1]), "r"(a[2]), "r"(a[3]), "r"(b[0]), "r"(b[1]));
}

__device__ __forceinline__ void mma_bf16(float* c, const uint32_t* a, const uint32_t* b) {
    asm volatile(
        "mma.sync.aligned.m16n8k16.row.col.f32.bf16.bf16.f32 "
        "{%0,%1,%2,%3}, {%4,%5,%6,%7}, {%8,%9}, {%0,%1,%2,%3};\n"
        : "+f"(c[0]), "+f"(c[1]), "+f"(c[2]), "+f"(c[3])
        : "r"(a[0]), "r"(a[1]), "r"(a[2]), "r"(a[3]), "r"(b[0]), "r"(b[1]));
}

__device__ __forceinline__ void cpa16(uint32_t s, const void* g) {
    asm volatile("cp.async.cg.shared.global [%0], [%1], 16;" :: "r"(s), "l"(g));
}

__device__ __forceinline__ void ldm_x4(uint32_t* r, uint32_t a) {
    asm volatile("ldmatrix.sync.aligned.m8n8.x4.shared.b16 {%0,%1,%2,%3}, [%4];"
        : "=r"(r[0]), "=r"(r[1]), "=r"(r[2]), "=r"(r[3]) : "r"(a));
}

__device__ __forceinline__ void ldm_x4_t(uint32_t* r, uint32_t a) {
    asm volatile("ldmatrix.sync.aligned.m8n8.x4.trans.shared.b16 {%0,%1,%2,%3}, [%4];"
        : "=r"(r[0]), "=r"(r[1]), "=r"(r[2]), "=r"(r[3]) : "r"(a));
}

// ---------------- prep: ALL weight mirrors in ONE launch -------------------------
#define NW4 (NLL*CC*CC/4)
#define NF4 ((size_t)NLL*FCC*CC/4)
__global__ void roundcpy6_kernel(
    const float4* __restrict__ a0, const float4* __restrict__ a1,
    const float4* __restrict__ a2, const float4* __restrict__ a3,
    const float4* __restrict__ a4, const float4* __restrict__ a5,
    float4* __restrict__ y0, float4* __restrict__ y1, float4* __restrict__ y2,
    float4* __restrict__ y3, float4* __restrict__ y4, float4* __restrict__ y5)
{
    size_t i = (size_t)blockIdx.x * 256 + threadIdx.x;
    const float4* src; float4* dst; size_t off;
    if (i < (size_t)4 * NW4) {
        int w = (int)(i / NW4); off = i % NW4;
        src = (w == 0) ? a0 : (w == 1) ? a1 : (w == 2) ? a2 : a3;
        dst = (w == 0) ? y0 : (w == 1) ? y1 : (w == 2) ? y2 : y3;
    } else {
        size_t j = i - (size_t)4 * NW4;
        int w = (int)(j / NF4); off = j % NF4;
        src = (w == 0) ? a4 : a5;
        dst = (w == 0) ? y4 : y5;
    }
    float4 v = src[off];
    v.x = rntf(v.x); v.y = rntf(v.y); v.z = rntf(v.z); v.w = rntf(v.w);
    dst[off] = v;
}

// ---------------- elementwise: px = x*mask (fp32), pxr = round(px) ---------------
__global__ void maskmul_kernel(const float* __restrict__ X, const float* __restrict__ msk,
                               float* __restrict__ Y, float* __restrict__ Yr) {
    int i = blockIdx.x * 256 + threadIdx.x;
    int l = i & (LL - 1);
    int b = i / (CC * LL);
    float v = X[i] * msk[b * LL + l];
    Y[i] = v;
    Yr[i] = rntf(v);
}

// mask -> additive bias (0 or -1e4) for attention columns
__global__ void maskbias_kernel(const float* __restrict__ msk, float* __restrict__ mb) {
    int i = blockIdx.x * 256 + threadIdx.x;
    mb[i] = (msk[i] == 0.f) ? -1e4f : 0.f;
}

// ---------------- tf32 tensor-core GEMM v7: unrolled-by-4 main loop --------------
#define APAD 20
#define BPAD 136
#define STG_A (128 * APAD)
#define STG_B (16 * BPAD)
#define NSTG 4
__global__ __launch_bounds__(256, 2) void gemm_tc_kernel(
    const float* __restrict__ W0, const float* __restrict__ W1p, const float* __restrict__ W2p,
    const float* __restrict__ c0, const float* __restrict__ c1, const float* __restrict__ c2,
    const float* __restrict__ X, const float* __restrict__ msk,
    float* __restrict__ Y0, float* __restrict__ Y1p, float* __restrict__ Y2p,
    int M, int N, int K, int flags)
{
    extern __shared__ float gsm[];
    float* As = gsm;
    float* Bs = gsm + NSTG * STG_A;

    const int tid  = threadIdx.x;
    const int mat  = blockIdx.z / BB;
    const int b    = blockIdx.z % BB;
    const bool splitk = flags & 8;
    const float* Wm   = (mat == 0) ? W0 : (mat == 1 ? W1p : W2p);
    const float* bias = (mat == 0) ? c0 : (mat == 1 ? c1 : c2);
    float*       Y    = (mat == 0) ? Y0 : (mat == 1 ? Y1p : Y2p);

    const int Keff = splitk ? (K >> 1) : K;
    const int kOff = splitk ? mat * Keff : 0;

    const int bm = blockIdx.y * 128, bn = blockIdx.x * 128;
    const float* mp = msk + (size_t)b * LL;

    const float* Ag = Wm + (size_t)bm * K + kOff;
    const float* Bg = X + (size_t)b * K * N + (size_t)kOff * N + bn;

    const int ar  = tid >> 2;
    const int akc = (tid & 3) * 4;
    const int bkk = tid >> 5;
    const int bn4 = (tid & 31) * 4;

    const uint32_t sA = (uint32_t)__cvta_generic_to_shared(As);
    const uint32_t sB = (uint32_t)__cvta_generic_to_shared(Bs);

    #define ISSUE(ST, K0) do { \
        cpa16(sA + (uint32_t)(((ST) * STG_A) + ar * APAD + akc) * 4, \
              Ag + (size_t)ar * K + (K0) + akc); \
        cpa16(sA + (uint32_t)(((ST) * STG_A) + (ar + 64) * APAD + akc) * 4, \
              Ag + (size_t)(ar + 64) * K + (K0) + akc); \
        cpa16(sB + (uint32_t)(((ST) * STG_B) + bkk * BPAD + bn4) * 4, \
              Bg + (size_t)((K0) + bkk) * N + bn4); \
        cpa16(sB + (uint32_t)(((ST) * STG_B) + (bkk + 8) * BPAD + bn4) * 4, \
              Bg + (size_t)((K0) + bkk + 8) * N + bn4); \
        asm volatile("cp.async.commit_group;" ::: "memory"); \
    } while (0)

    const int lane = tid & 31, warp = tid >> 5;
    const int wm = (warp >> 2) * 64;
    const int wn = (warp & 3) * 32;
    const int lm = lane >> 2, lk = lane & 3;
    const int mrow = (lane & 7) + ((lane >> 3) & 1) * 8;
    const int kadd = (lane >> 4) * 4;

    float acc[4][4][4];
    #pragma unroll
    for (int i = 0; i < 4; i++)
        #pragma unroll
        for (int j = 0; j < 4; j++)
            #pragma unroll
            for (int r = 0; r < 4; r++) acc[i][j][r] = 0.f;

    const int nIter = Keff / 16;     // always a multiple of 4 here (16 or 32)
    ISSUE(0, 0);
    ISSUE(1, 16);
    ISSUE(2, 32);

    for (int it4 = 0; it4 < nIter; it4 += 4) {
        #pragma unroll
        for (int u = 0; u < 4; u++) {
            const int it = it4 + u;
            asm volatile("cp.async.wait_group 2;" ::: "memory");
            __syncthreads();
            if (it + 3 < nIter) ISSUE((u + 3) & 3, (it + 3) * 16);
            else asm volatile("cp.async.commit_group;" ::: "memory");

            // buf == u (literal): all smem addressing is compile-time constant
            const uint32_t aBase = sA + (uint32_t)(u * STG_A) * 4;
            const float* Bb = Bs + u * STG_B;
            #pragma unroll
            for (int ks = 0; ks < 16; ks += 8) {
                uint32_t a[4][4], bfr[4][2];
                #pragma unroll
                for (int mt = 0; mt < 4; mt++)
                    ldm_x4(a[mt], aBase + (uint32_t)((wm + mt*16 + mrow) * APAD + ks + kadd) * 4);
                #pragma unroll
                for (int nt = 0; nt < 4; nt++) {
                    bfr[nt][0] = __float_as_uint(Bb[(ks + lk    ) * BPAD + wn + nt*8 + lm]);
                    bfr[nt][1] = __float_as_uint(Bb[(ks + lk + 4) * BPAD + wn + nt*8 + lm]);
                }
                #pragma unroll
                for (int mt = 0; mt < 4; mt++)
                    #pragma unroll
                    for (int nt = 0; nt < 4; nt++)
                        mma_tf32(acc[mt][nt], a[mt], bfr[nt]);
            }
        }
    }
    #undef ISSUE

    const bool relu = flags & 2;
    const bool omask = flags & 4;
    const bool rnd = flags & 16;
    const bool h16 = (flags & 32) && (mat >= 1);
    float* Yb = Y + (size_t)b * M * N;
    __nv_bfloat16* Yh = (__nv_bfloat16*)Y + (size_t)b * M * N;
    #pragma unroll
    for (int mt = 0; mt < 4; mt++) {
        #pragma unroll
        for (int half = 0; half < 2; half++) {
            int m = bm + wm + mt * 16 + lm + half * 8;
            float bv = bias[m];
            #pragma unroll
            for (int nt = 0; nt < 4; nt++) {
                int n = bn + wn + nt * 8 + lk * 2;
                float v0 = acc[mt][nt][half * 2 + 0] + bv;
                float v1 = acc[mt][nt][half * 2 + 1] + bv;
                if (relu) { v0 = fmaxf(v0, 0.f); v1 = fmaxf(v1, 0.f); }
                if (omask) { v0 *= mp[n]; v1 *= mp[n + 1]; }
                if (h16) {
                    *(__nv_bfloat162*)&Yh[(size_t)m * N + n] = __floats2bfloat162_rn(v0, v1);
                } else {
                    if (rnd) { v0 = rntf(v0); v1 = rntf(v1); }
                    *(float2*)&Yb[(size_t)m * N + n] = make_float2(v0, v1);
                }
            }
        }
    }
}

// ---------------- tensor-core flash attention v9 ---------------------------------
// No-max softmax; additive column mask bias (precomputed); NO row masking
// (masked rows' garbage lives only at masked positions, zeroed by final mask).
// P in registers, warp-uniform window skip, 2 CTAs/SM.
#define KSTRH 72                  // bf16 units (144B pitch)
#define KTILEH (64 * KSTRH)
#define VSTRH 72
#define VTILEH (64 * VSTRH)
__global__ __launch_bounds__(256, 2) void attn_tc_kernel(
    const float* __restrict__ Q, const __nv_bfloat16* __restrict__ Kk,
    const __nv_bfloat16* __restrict__ V, const float* __restrict__ mbias,
    const float* __restrict__ relk, const float* __restrict__ relv,
    float* __restrict__ O)
{
    extern __shared__ float smem[];
    float* qs = smem;                                     // [128][73] fp32
    __nv_bfloat16* ksh = (__nv_bfloat16*)(qs + 128 * 73); // 3 x [64][72] bf16
    __nv_bfloat16* vsh = ksh + 3 * KTILEH;                // 3 x [64][72] bf16
    float* rks   = (float*)(vsh + 3 * VTILEH);            // [9][64]
    float* rvs   = rks   + 9 * 64;                        // [9][64]
    float* relb  = rvs   + 9 * 64;                        // [128][12]
    float* pwin  = relb  + 128 * 12;                      // [128][12]
    float* invli = pwin  + 128 * 12;                      // [128]
    float* msksb = invli + 128;                           // 3 x [64] additive bias

    const int tid = threadIdx.x;
    const int lane = tid & 31, warp = tid >> 5;
    const int b = blockIdx.z, h = blockIdx.y;
    const int l0 = blockIdx.x * 128;

    const float* qp = Q  + ((size_t)b * CC + h * DD) * LL;
    const __nv_bfloat16* kph = Kk + ((size_t)b * CC + h * DD) * LL;
    const __nv_bfloat16* vph = V + ((size_t)b * CC + h * DD) * LL;
    const float* mbp = mbias + (size_t)b * LL;

    const uint32_t sK = (uint32_t)__cvta_generic_to_shared(ksh);
    const uint32_t sV = (uint32_t)__cvta_generic_to_shared(vsh);
    const uint32_t sM = (uint32_t)__cvta_generic_to_shared(msksb);

    #define AISSUE(ST, T) do { \
        const int _m0 = (T) * 64; \
        _Pragma("unroll") \
        for (int i = 0; i < 2; i++) { \
            int ch = i * 256 + tid; \
            int vd = ch >> 3, vm = (ch & 7) * 8; \
            cpa16(sK + (uint32_t)((ST) * KTILEH + vd * KSTRH + vm) * 2, \
                  kph + (size_t)vd * LL + _m0 + vm); \
            cpa16(sV + (uint32_t)((ST) * VTILEH + vd * VSTRH + vm) * 2, \
                  vph + (size_t)vd * LL + _m0 + vm); \
        } \
        if (tid < 16) cpa16(sM + (uint32_t)((ST) * 64 + tid * 4) * 4, mbp + _m0 + tid * 4); \
        asm volatile("cp.async.commit_group;" ::: "memory"); \
    } while (0)

    AISSUE(0, 0);
    AISSUE(1, 1);

    // ---- stage Q (transpose, scaled), rel tables, zero pwin ----
    #pragma unroll
    for (int i = 0; i < 8; i++) {
        int d = (tid >> 5) + i * 8;
        int l = (tid & 31) * 4;
        float4 qv = *(const float4*)&qp[(size_t)d * LL + l0 + l];
        qs[(l+0)*73 + d] = qv.x * SCALEC;
        qs[(l+1)*73 + d] = qv.y * SCALEC;
        qs[(l+2)*73 + d] = qv.z * SCALEC;
        qs[(l+3)*73 + d] = qv.w * SCALEC;
    }
    for (int i = tid; i < 9 * 64; i += 256) { rks[i] = relk[i]; rvs[i] = relv[i]; }
    for (int i = tid; i < 128 * 12; i += 256) pwin[i] = 0.f;
    __syncthreads();

    // relbias[l][df] = q_scaled[l] . rel_k[df]  (fp32)
    for (int i = tid; i < 128 * 9; i += 256) {
        int l = i / 9, df = i % 9;
        const float* qq = &qs[l * 73];
        const float* rr = &rks[df * 64];
        float a = 0.f;
        #pragma unroll 16
        for (int d = 0; d < DD; d++) a = fmaf(qq[d], rr[d], a);
        relb[l * 12 + df] = a;
    }

    const int r0 = warp * 16 + (lane >> 2);
    const int r1 = r0 + 8;
    const int lk = lane & 3, lm = lane >> 2;

    // hoist Q as bf16 m16n8k16 A fragments
    uint32_t qf[4][4];
    #pragma unroll
    for (int c = 0; c < 4; c++) {
        int kb = c * 16 + 2 * lk;
        qf[c][0] = packbf2(qs[r0*73 + kb    ], qs[r0*73 + kb + 1]);
        qf[c][1] = packbf2(qs[r1*73 + kb    ], qs[r1*73 + kb + 1]);
        qf[c][2] = packbf2(qs[r0*73 + kb + 8], qs[r0*73 + kb + 9]);
        qf[c][3] = packbf2(qs[r1*73 + kb + 8], qs[r1*73 + kb + 9]);
    }

    // ldmatrix lane addressing
    const uint32_t vBrowBase = (uint32_t)(((lane >> 4) & 1) * 8 + (lane & 7));
    const uint32_t vBcol = (uint32_t)(((lane >> 3) & 1) * 16);
    const uint32_t kBrow = (uint32_t)(((lane >> 3) & 1) * 8 + (lane & 7));
    const uint32_t kBnb  = (uint32_t)(((lane >> 4) & 1) * 8);

    float co[8][4];
    #pragma unroll
    for (int nt = 0; nt < 8; nt++)
        #pragma unroll
        for (int j = 0; j < 4; j++) co[nt][j] = 0.f;
    float li0 = 0.f, li1 = 0.f;

    const int wrow = l0 + warp * 16;

    const int NT = LL / 64;
    for (int t = 0; t < NT; t++) {
        const int m0 = t * 64;
        asm volatile("cp.async.wait_group 1;" ::: "memory");
        __syncthreads();
        if (t + 2 < NT) AISSUE((t + 2) % 3, t + 2);
        else asm volatile("cp.async.commit_group;" ::: "memory");

        const int buf = t % 3;
        const uint32_t kbase = sK + (uint32_t)(buf * KTILEH) * 2;
        const uint32_t vbase = sV + (uint32_t)(buf * VTILEH) * 2;
        const float* msks = msksb + buf * 64;

        const bool haswin = (m0 + 63 >= wrow - WW) && (m0 <= wrow + 15 + WW);

        // ---- S = Q K^T (bf16) ----
        float s[8][4];
        #pragma unroll
        for (int nt = 0; nt < 8; nt++)
            #pragma unroll
            for (int j = 0; j < 4; j++) s[nt][j] = 0.f;

        #pragma unroll
        for (int kk2 = 0; kk2 < 4; kk2++) {
            #pragma unroll
            for (int ntp = 0; ntp < 4; ntp++) {
                uint32_t bk[4];
                ldm_x4_t(bk, kbase + ((uint32_t)(kk2*16) + kBrow) * (KSTRH*2)
                             + ((uint32_t)(ntp*16) + kBnb) * 2);
                mma_bf16(s[2*ntp    ], qf[kk2], bk);
                mma_bf16(s[2*ntp + 1], qf[kk2], bk + 2);
            }
        }

        // ---- rel_k bias (window tiles only) + additive column mask ----
        const int gl0 = l0 + r0, gl1 = l0 + r1;
        if (haswin) {
            #pragma unroll
            for (int nt = 0; nt < 8; nt++) {
                #pragma unroll
                for (int j = 0; j < 2; j++) {
                    int gm = m0 + nt*8 + 2*lk + j;
                    int df0 = gm - gl0;
                    if (df0 >= -WW && df0 <= WW) s[nt][j] += relb[r0*12 + df0 + WW];
                    int df1 = gm - gl1;
                    if (df1 >= -WW && df1 <= WW) s[nt][2+j] += relb[r1*12 + df1 + WW];
                }
            }
        }
        #pragma unroll
        for (int nt = 0; nt < 8; nt++) {
            #pragma unroll
            for (int j = 0; j < 2; j++) {
                float mb = msks[nt*8 + 2*lk + j];
                s[nt][j] += mb;
                s[nt][2+j] += mb;
            }
        }

        // ---- no-max softmax: p = exp(s); masked -> exp(-1e4) = 0 ----
        #pragma unroll
        for (int nt = 0; nt < 8; nt++) {
            s[nt][0] = __expf(s[nt][0]); s[nt][1] = __expf(s[nt][1]);
            s[nt][2] = __expf(s[nt][2]); s[nt][3] = __expf(s[nt][3]);
            li0 += s[nt][0] + s[nt][1];
            li1 += s[nt][2] + s[nt][3];
        }

        // record window probs (final values)
        if (haswin) {
            #pragma unroll
            for (int nt = 0; nt < 8; nt++) {
                #pragma unroll
                for (int j = 0; j < 2; j++) {
                    int gm = m0 + nt*8 + 2*lk + j;
                    int df0 = gm - gl0;
                    if (df0 >= -WW && df0 <= WW) pwin[r0*12 + df0 + WW] = s[nt][j];
                    int df1 = gm - gl1;
                    if (df1 >= -WW && df1 <= WW) pwin[r1*12 + df1 + WW] = s[nt][2+j];
                }
            }
        }

        // ---- O += P V : A-fragments packed directly from S registers ----
        #pragma unroll
        for (int kk2 = 0; kk2 < 4; kk2++) {
            uint32_t a[4];
            a[0] = packbf2(s[2*kk2  ][0], s[2*kk2  ][1]);
            a[1] = packbf2(s[2*kk2  ][2], s[2*kk2  ][3]);
            a[2] = packbf2(s[2*kk2+1][0], s[2*kk2+1][1]);
            a[3] = packbf2(s[2*kk2+1][2], s[2*kk2+1][3]);
            #pragma unroll
            for (int ntp = 0; ntp < 4; ntp++) {
                uint32_t bv[4];
                uint32_t vrow = (uint32_t)(2*ntp*8) + vBrowBase;
                ldm_x4(bv, vbase + vrow * (VSTRH*2) + (uint32_t)(kk2*32) + vBcol);
                mma_bf16(co[2*ntp    ], a, bv);
                mma_bf16(co[2*ntp + 1], a, bv + 2);
            }
        }
    }
    #undef AISSUE

    // ---- reduce li across the 4 lanes of each row group (once) ----
    li0 += __shfl_xor_sync(0xffffffffu, li0, 1);
    li0 += __shfl_xor_sync(0xffffffffu, li0, 2);
    li1 += __shfl_xor_sync(0xffffffffu, li1, 1);
    li1 += __shfl_xor_sync(0xffffffffu, li1, 2);

    // ---- epilogue ----
    __syncthreads();
    float* outb = (float*)ksh;
    float inv0 = 1.0f / fmaxf(li0, 1e-20f);
    float inv1 = 1.0f / fmaxf(li1, 1e-20f);
    if (lk == 0) { invli[r0] = inv0; invli[r1] = inv1; }
    #pragma unroll
    for (int nt = 0; nt < 8; nt++) {
        int c = nt*8 + 2*lk;
        outb[r0*73 + c    ] = co[nt][0] * inv0;
        outb[r0*73 + c + 1] = co[nt][1] * inv0;
        outb[r1*73 + c    ] = co[nt][2] * inv1;
        outb[r1*73 + c + 1] = co[nt][3] * inv1;
    }
    __syncthreads();

    float* op = O + ((size_t)b * CC + h * DD) * LL;
    #pragma unroll
    for (int i = 0; i < 32; i++) {
        int idx = i * 256 + tid;
        int l = idx & 127;
        int d = idx >> 7;
        float r = 0.f;
        #pragma unroll
        for (int df = 0; df < 9; df++) r = fmaf(pwin[l*12 + df], rvs[df*64 + d], r);
        op[(size_t)d * LL + l0 + l] = rntf(outb[l*73 + d] + invli[l] * r);
    }
}

// ---------- fused residual add (2 deltas) + LayerNorm, smem-cached ---------------
__global__ void add_ln_kernel(const float* __restrict__ X, const float* __restrict__ D0,
                              const float* __restrict__ D1,
                              const float* __restrict__ gam, const float* __restrict__ bet,
                              float* __restrict__ Yo, float* __restrict__ Yr,
                              float* __restrict__ Yext, const float* __restrict__ fm)
{
    __shared__ float vbuf[CC][17];
    __shared__ float sm[16][17], sq[16][17];
    int b = blockIdx.y;
    int l = blockIdx.x * 16 + threadIdx.x;
    int cg = threadIdx.y;
    int lx = threadIdx.x;
    const size_t base = (size_t)b * CC * LL + l;

    float s = 0.f, s2 = 0.f;
    for (int c = cg; c < CC; c += 16) {
        float v = X[base + (size_t)c * LL] + D0[base + (size_t)c * LL] + D1[base + (size_t)c * LL];
        vbuf[c][lx] = v;
        s += v; s2 += v * v;
    }
    sm[cg][lx] = s; sq[cg][lx] = s2;
    __syncthreads();
    float ts = 0.f, ts2 = 0.f;
    #pragma unroll
    for (int i = 0; i < 16; i++) { ts += sm[i][lx]; ts2 += sq[i][lx]; }
    float mean = ts * (1.0f / CC);
    float var  = ts2 * (1.0f / CC) - mean * mean;
    float rstd = rsqrtf(var + EPSC);
    float mval = Yext ? fm[(size_t)b * LL + l] : 0.f;
    for (int c = cg; c < CC; c += 16) {
        float v = vbuf[c][lx];
        float y = (v - mean) * rstd * gam[c] + bet[c];
        Yo[base + (size_t)c * LL] = y;
        Yr[base + (size_t)c * LL] = rntf(y);
        if (Yext) Yext[base + (size_t)c * LL] = y * mval;
    }
}

// ---------------- host orchestration -------------------------------------------
extern "C" void kernel_launch(void* const* d_in, const int* in_sizes, int n_in,
                              void* d_out, int out_size)
{
    const float* x    = (const float*)d_in[0];
    const float* mask = (const float*)d_in[1];
    const float* wq = (const float*)d_in[2];  const float* bq = (const float*)d_in[3];
    const float* wk = (const float*)d_in[4];  const float* bk = (const float*)d_in[5];
    const float* wv = (const float*)d_in[6];  const float* bv = (const float*)d_in[7];
    const float* wo = (const float*)d_in[8];  const float* bo = (const float*)d_in[9];
    const float* relk = (const float*)d_in[10];
    const float* relv = (const float*)d_in[11];
    const float* ln1g = (const float*)d_in[12]; const float* ln1b = (const float*)d_in[13];
    const float* w1 = (const float*)d_in[14]; const float* b1 = (const float*)d_in[15];
    const float* w2 = (const float*)d_in[16]; const float* b2 = (const float*)d_in[17];
    const float* ln2g = (const float*)d_in[18]; const float* ln2b = (const float*)d_in[19];

    float *px, *pxr, *pq, *pk, *pv, *pa, *pt, *ph, *pz, *pmb;
    float *rwq, *rwk, *rwv, *rwo, *rw1, *rw2;
    cudaGetSymbolAddress((void**)&px, g_x);
    cudaGetSymbolAddress((void**)&pxr, g_xr);
    cudaGetSymbolAddress((void**)&pq, g_q);
    cudaGetSymbolAddress((void**)&pk, g_k);
    cudaGetSymbolAddress((void**)&pv, g_v);
    cudaGetSymbolAddress((void**)&pa, g_a);
    cudaGetSymbolAddress((void**)&pt, g_t);
    cudaGetSymbolAddress((void**)&ph, g_h);
    cudaGetSymbolAddress((void**)&pz, g_zero);
    cudaGetSymbolAddress((void**)&pmb, g_mb);
    cudaGetSymbolAddress((void**)&rwq, g_rwq);
    cudaGetSymbolAddress((void**)&rwk, g_rwk);
    cudaGetSymbolAddress((void**)&rwv, g_rwv);
    cudaGetSymbolAddress((void**)&rwo, g_rwo);
    cudaGetSymbolAddress((void**)&rw1, g_rw1);
    cudaGetSymbolAddress((void**)&rw2, g_rw2);
    float* pt2 = pk;   // split-K partial #2

    const size_t attn_smem = (size_t)(128*73) * 4
                           + (size_t)(3*KTILEH + 3*VTILEH) * 2
                           + (size_t)(9*64*2 + 128*12*2 + 128 + 3*64) * 4;
    cudaFuncSetAttribute(attn_tc_kernel, cudaFuncAttributeMaxDynamicSharedMemorySize, (int)attn_smem);
    const size_t gemm_smem = (size_t)(NSTG * STG_A + NSTG * STG_B) * sizeof(float);
    cudaFuncSetAttribute(gemm_tc_kernel, cudaFuncAttributeMaxDynamicSharedMemorySize, (int)gemm_smem);

    const size_t totalF4 = (size_t)4 * NW4 + 2 * NF4;
    roundcpy6_kernel<<<(unsigned)(totalF4 / 256), 256>>>(
        (const float4*)wq, (const float4*)wk, (const float4*)wv, (const float4*)wo,
        (const float4*)w1, (const float4*)w2,
        (float4*)rwq, (float4*)rwk, (float4*)rwv, (float4*)rwo,
        (float4*)rw1, (float4*)rw2);

    const int nElem = BB * CC * LL;
    maskmul_kernel<<<nElem / 256, 256>>>(x, mask, px, pxr);
    maskbias_kernel<<<BB * LL / 256, 256>>>(mask, pmb);

    dim3 gQKV(LL / 128, CC / 128, 3 * BB);
    dim3 gSK(LL / 128, CC / 128, 2 * BB);
    dim3 gF1(LL / 128, FCC / 128, BB);
    dim3 gAttn(LL / 128, HH, BB);
    dim3 gLN(LL / 16, BB);
    dim3 bLN(16, 16);

    for (int i = 0; i < NLL; i++) {
        const float* Wq = rwq + (size_t)i * CC * CC;
        const float* Wk = rwk + (size_t)i * CC * CC;
        const float* Wv = rwv + (size_t)i * CC * CC;
        const float* Wo = rwo + (size_t)i * CC * CC;
        const float* W1 = rw1 + (size_t)i * FCC * CC;
        const float* W2 = rw2 + (size_t)i * CC * FCC;
        const bool last = (i == NLL - 1);

        gemm_tc_kernel<<<gQKV, 256, gemm_smem>>>(Wq, Wk, Wv, bq + i*CC, bk + i*CC, bv + i*CC,
                                                 pxr, mask, pq, pk, pv, CC, LL, CC, 16 | 32);

        attn_tc_kernel<<<gAttn, 256, attn_smem>>>(pq, (const __nv_bfloat16*)pk,
                                                  (const __nv_bfloat16*)pv, pmb,
                                                  relk + (size_t)i * 9 * DD,
                                                  relv + (size_t)i * 9 * DD, pa);

        gemm_tc_kernel<<<gSK, 256, gemm_smem>>>(Wo, Wo, Wo, bo + i*CC, pz, pz,
                                                pa, mask, pt, pt2, pt2, CC, LL, CC, 8);
        add_ln_kernel<<<gLN, bLN>>>(px, pt, pt2, ln1g + i*CC, ln1b + i*CC,
                                    px, pxr, nullptr, mask);

        gemm_tc_kernel<<<gF1, 256, gemm_smem>>>(W1, W1, W1, b1 + i*FCC, b1 + i*FCC, b1 + i*FCC,
                                                pxr, mask, ph, ph, ph, FCC, LL, CC, 2 | 4 | 16);
        gemm_tc_kernel<<<gSK, 256, gemm_smem>>>(W2, W2, W2, b2 + i*CC, pz, pz,
                                                ph, mask, pt, pt2, pt2, CC, LL, FCC, 8 | 4);
        add_ln_kernel<<<gLN, bLN>>>(px, pt, pt2, ln2g + i*CC, ln2b + i*CC,
                                    px, pxr, last ? (float*)d_out : nullptr, mask);
    }
}

// round 17
// speedup vs baseline: 1.4888x; 1.0113x over previous
#include <cuda_runtime.h>
#include <cuda_bf16.h>
#include <stdint.h>

#define BB  4
#define CC  512
#define LL  1024
#define HH  8
#define DD  64
#define FCC 2048
#define NLL 4
#define WW  4
#define EPSC 1e-6f
#define SCALEC 0.125f   // 64^-0.5
#define SCALE2 (0.125f * 1.44269504f)   // 64^-0.5 * log2(e)

// ---------------- scratch (static device memory; no allocations) ----------------
__device__ float g_x[BB*CC*LL];     // residual stream, full fp32
__device__ float g_xr[BB*CC*LL];    // tf32-rounded mirror of residual (GEMM operand)
__device__ float g_q[BB*CC*LL];
__device__ float g_k[BB*CC*LL];     // K bf16 (half used); reused as split-K partial #2
__device__ float g_v[BB*CC*LL];     // V bf16 (half used)
__device__ float g_a[BB*CC*LL];
__device__ float g_t[BB*CC*LL];
__device__ float g_h[(size_t)BB*FCC*LL];
__device__ float g_zero[CC];        // zero-initialized (bias for split-K part 1)
__device__ float g_mb[BB*LL];       // additive mask bias (log2-domain): 0 or -1.5e4
__device__ int   g_mbflag[BB*(LL/64)];  // per 64-col tile: any masked?
// tf32-rounded weight mirrors
__device__ float g_rwq[NLL*CC*CC];
__device__ float g_rwk[NLL*CC*CC];
__device__ float g_rwv[NLL*CC*CC];
__device__ float g_rwo[NLL*CC*CC];
__device__ float g_rw1[(size_t)NLL*FCC*CC];
__device__ float g_rw2[(size_t)NLL*FCC*CC];

// ---------------- helpers --------------------------------------------------------
__device__ __forceinline__ uint32_t f2tf(float x) {
    uint32_t t;
    asm volatile("cvt.rna.tf32.f32 %0, %1;" : "=r"(t) : "f"(x));
    return t;
}
__device__ __forceinline__ float rntf(float x) { return __uint_as_float(f2tf(x)); }

__device__ __forceinline__ float ex2(float x) {
    float r;
    asm("ex2.approx.ftz.f32 %0, %1;" : "=f"(r) : "f"(x));
    return r;
}

__device__ __forceinline__ uint32_t packbf2(float lo, float hi) {
    __nv_bfloat162 h = __floats2bfloat162_rn(lo, hi);
    return *(uint32_t*)&h;
}

__device__ __forceinline__ void mma_tf32(float* c, const uint32_t* a, const uint32_t* b) {
    asm volatile(
        "mma.sync.aligned.m16n8k8.row.col.f32.tf32.tf32.f32 "
        "{%0,%1,%2,%3}, {%4,%5,%6,%7}, {%8,%9}, {%0,%1,%2,%3};\n"
        : "+f"(c[0]), "+f"(c[1]), "+f"(c[2]), "+f"(c[3])
        : "r"(a[0]), "r"(a[1]), "r"(a[2]), "r"(a[3]), "r"(b[0]), "r"(b[1]));
}

__device__ __forceinline__ void mma_bf16(float* c, const uint32_t* a, const uint32_t* b) {
    asm volatile(
        "mma.sync.aligned.m16n8k16.row.col.f32.bf16.bf16.f32 "
        "{%0,%1,%2,%3}, {%4,%5,%6,%7}, {%8,%9}, {%0,%1,%2,%3};\n"
        : "+f"(c[0]), "+f"(c[1]), "+f"(c[2]), "+f"(c[3])
        : "r"(a[0]), "r"(a[1]), "r"(a[2]), "r"(a[3]), "r"(b[0]), "r"(b[1]));
}

__device__ __forceinline__ void cpa16(uint32_t s, const void* g) {
    asm volatile("cp.async.cg.shared.global [%0], [%1], 16;" :: "r"(s), "l"(g));
}

__device__ __forceinline__ void ldm_x4(uint32_t* r, uint32_t a) {
    asm volatile("ldmatrix.sync.aligned.m8n8.x4.shared.b16 {%0,%1,%2,%3}, [%4];"
        : "=r"(r[0]), "=r"(r[1]), "=r"(r[2]), "=r"(r[3]) : "r"(a));
}

__device__ __forceinline__ void ldm_x4_t(uint32_t* r, uint32_t a) {
    asm volatile("ldmatrix.sync.aligned.m8n8.x4.trans.shared.b16 {%0,%1,%2,%3}, [%4];"
        : "=r"(r[0]), "=r"(r[1]), "=r"(r[2]), "=r"(r[3]) : "r"(a));
}

// ---------------- prep: ALL weight mirrors in ONE launch -------------------------
#define NW4 (NLL*CC*CC/4)
#define NF4 ((size_t)NLL*FCC*CC/4)
__global__ void roundcpy6_kernel(
    const float4* __restrict__ a0, const float4* __restrict__ a1,
    const float4* __restrict__ a2, const float4* __restrict__ a3,
    const float4* __restrict__ a4, const float4* __restrict__ a5,
    float4* __restrict__ y0, float4* __restrict__ y1, float4* __restrict__ y2,
    float4* __restrict__ y3, float4* __restrict__ y4, float4* __restrict__ y5)
{
    size_t i = (size_t)blockIdx.x * 256 + threadIdx.x;
    const float4* src; float4* dst; size_t off;
    if (i < (size_t)4 * NW4) {
        int w = (int)(i / NW4); off = i % NW4;
        src = (w == 0) ? a0 : (w == 1) ? a1 : (w == 2) ? a2 : a3;
        dst = (w == 0) ? y0 : (w == 1) ? y1 : (w == 2) ? y2 : y3;
    } else {
        size_t j = i - (size_t)4 * NW4;
        int w = (int)(j / NF4); off = j % NF4;
        src = (w == 0) ? a4 : a5;
        dst = (w == 0) ? y4 : y5;
    }
    float4 v = src[off];
    v.x = rntf(v.x); v.y = rntf(v.y); v.z = rntf(v.z); v.w = rntf(v.w);
    dst[off] = v;
}

// ---------------- elementwise: px = x*mask (fp32), pxr = round(px) ---------------
__global__ void maskmul_kernel(const float* __restrict__ X, const float* __restrict__ msk,
                               float* __restrict__ Y, float* __restrict__ Yr) {
    int i = blockIdx.x * 256 + threadIdx.x;
    int l = i & (LL - 1);
    int b = i / (CC * LL);
    float v = X[i] * msk[b * LL + l];
    Y[i] = v;
    Yr[i] = rntf(v);
}

// mask -> additive log2-domain bias + per-tile any-masked flag
__global__ void maskbias_kernel(const float* __restrict__ msk, float* __restrict__ mb,
                                int* __restrict__ flags) {
    int tile = blockIdx.x;                 // 0 .. BB*16-1
    int i = tile * 64 + threadIdx.x;
    float m = msk[i];
    mb[i] = (m == 0.f) ? -1.5e4f : 0.f;
    int anyz = __syncthreads_or(m == 0.f);
    if (threadIdx.x == 0) flags[tile] = anyz;
}

// ---------------- tf32 tensor-core GEMM v7 (unchanged from R16) ------------------
#define APAD 20
#define BPAD 136
#define STG_A (128 * APAD)
#define STG_B (16 * BPAD)
#define NSTG 4
__global__ __launch_bounds__(256, 2) void gemm_tc_kernel(
    const float* __restrict__ W0, const float* __restrict__ W1p, const float* __restrict__ W2p,
    const float* __restrict__ c0, const float* __restrict__ c1, const float* __restrict__ c2,
    const float* __restrict__ X, const float* __restrict__ msk,
    float* __restrict__ Y0, float* __restrict__ Y1p, float* __restrict__ Y2p,
    int M, int N, int K, int flags)
{
    extern __shared__ float gsm[];
    float* As = gsm;
    float* Bs = gsm + NSTG * STG_A;

    const int tid  = threadIdx.x;
    const int mat  = blockIdx.z / BB;
    const int b    = blockIdx.z % BB;
    const bool splitk = flags & 8;
    const float* Wm   = (mat == 0) ? W0 : (mat == 1 ? W1p : W2p);
    const float* bias = (mat == 0) ? c0 : (mat == 1 ? c1 : c2);
    float*       Y    = (mat == 0) ? Y0 : (mat == 1 ? Y1p : Y2p);

    const int Keff = splitk ? (K >> 1) : K;
    const int kOff = splitk ? mat * Keff : 0;

    const int bm = blockIdx.y * 128, bn = blockIdx.x * 128;
    const float* mp = msk + (size_t)b * LL;

    const float* Ag = Wm + (size_t)bm * K + kOff;
    const float* Bg = X + (size_t)b * K * N + (size_t)kOff * N + bn;

    const int ar  = tid >> 2;
    const int akc = (tid & 3) * 4;
    const int bkk = tid >> 5;
    const int bn4 = (tid & 31) * 4;

    const uint32_t sA = (uint32_t)__cvta_generic_to_shared(As);
    const uint32_t sB = (uint32_t)__cvta_generic_to_shared(Bs);

    #define ISSUE(ST, K0) do { \
        cpa16(sA + (uint32_t)(((ST) * STG_A) + ar * APAD + akc) * 4, \
              Ag + (size_t)ar * K + (K0) + akc); \
        cpa16(sA + (uint32_t)(((ST) * STG_A) + (ar + 64) * APAD + akc) * 4, \
              Ag + (size_t)(ar + 64) * K + (K0) + akc); \
        cpa16(sB + (uint32_t)(((ST) * STG_B) + bkk * BPAD + bn4) * 4, \
              Bg + (size_t)((K0) + bkk) * N + bn4); \
        cpa16(sB + (uint32_t)(((ST) * STG_B) + (bkk + 8) * BPAD + bn4) * 4, \
              Bg + (size_t)((K0) + bkk + 8) * N + bn4); \
        asm volatile("cp.async.commit_group;" ::: "memory"); \
    } while (0)

    const int lane = tid & 31, warp = tid >> 5;
    const int wm = (warp >> 2) * 64;
    const int wn = (warp & 3) * 32;
    const int lm = lane >> 2, lk = lane & 3;
    const int mrow = (lane & 7) + ((lane >> 3) & 1) * 8;
    const int kadd = (lane >> 4) * 4;

    float acc[4][4][4];
    #pragma unroll
    for (int i = 0; i < 4; i++)
        #pragma unroll
        for (int j = 0; j < 4; j++)
            #pragma unroll
            for (int r = 0; r < 4; r++) acc[i][j][r] = 0.f;

    const int nIter = Keff / 16;
    ISSUE(0, 0);
    ISSUE(1, 16);
    ISSUE(2, 32);

    for (int it4 = 0; it4 < nIter; it4 += 4) {
        #pragma unroll
        for (int u = 0; u < 4; u++) {
            const int it = it4 + u;
            asm volatile("cp.async.wait_group 2;" ::: "memory");
            __syncthreads();
            if (it + 3 < nIter) ISSUE((u + 3) & 3, (it + 3) * 16);
            else asm volatile("cp.async.commit_group;" ::: "memory");

            const uint32_t aBase = sA + (uint32_t)(u * STG_A) * 4;
            const float* Bb = Bs + u * STG_B;
            #pragma unroll
            for (int ks = 0; ks < 16; ks += 8) {
                uint32_t a[4][4], bfr[4][2];
                #pragma unroll
                for (int mt = 0; mt < 4; mt++)
                    ldm_x4(a[mt], aBase + (uint32_t)((wm + mt*16 + mrow) * APAD + ks + kadd) * 4);
                #pragma unroll
                for (int nt = 0; nt < 4; nt++) {
                    bfr[nt][0] = __float_as_uint(Bb[(ks + lk    ) * BPAD + wn + nt*8 + lm]);
                    bfr[nt][1] = __float_as_uint(Bb[(ks + lk + 4) * BPAD + wn + nt*8 + lm]);
                }
                #pragma unroll
                for (int mt = 0; mt < 4; mt++)
                    #pragma unroll
                    for (int nt = 0; nt < 4; nt++)
                        mma_tf32(acc[mt][nt], a[mt], bfr[nt]);
            }
        }
    }
    #undef ISSUE

    const bool relu = flags & 2;
    const bool omask = flags & 4;
    const bool rnd = flags & 16;
    const bool h16 = (flags & 32) && (mat >= 1);
    float* Yb = Y + (size_t)b * M * N;
    __nv_bfloat16* Yh = (__nv_bfloat16*)Y + (size_t)b * M * N;
    #pragma unroll
    for (int mt = 0; mt < 4; mt++) {
        #pragma unroll
        for (int half = 0; half < 2; half++) {
            int m = bm + wm + mt * 16 + lm + half * 8;
            float bv = bias[m];
            #pragma unroll
            for (int nt = 0; nt < 4; nt++) {
                int n = bn + wn + nt * 8 + lk * 2;
                float v0 = acc[mt][nt][half * 2 + 0] + bv;
                float v1 = acc[mt][nt][half * 2 + 1] + bv;
                if (relu) { v0 = fmaxf(v0, 0.f); v1 = fmaxf(v1, 0.f); }
                if (omask) { v0 *= mp[n]; v1 *= mp[n + 1]; }
                if (h16) {
                    *(__nv_bfloat162*)&Yh[(size_t)m * N + n] = __floats2bfloat162_rn(v0, v1);
                } else {
                    if (rnd) { v0 = rntf(v0); v1 = rntf(v1); }
                    *(float2*)&Yb[(size_t)m * N + n] = make_float2(v0, v1);
                }
            }
        }
    }
}

// ---------------- tensor-core flash attention v10 --------------------------------
// log2-domain no-max softmax (Q pre-scaled by log2e -> single ex2 per element);
// warp-uniform per-tile mask skip via precomputed flags; P in registers;
// window skip; 2 CTAs/SM.
#define KSTRH 72                  // bf16 units (144B pitch)
#define KTILEH (64 * KSTRH)
#define VSTRH 72
#define VTILEH (64 * VSTRH)
__global__ __launch_bounds__(256, 2) void attn_tc_kernel(
    const float* __restrict__ Q, const __nv_bfloat16* __restrict__ Kk,
    const __nv_bfloat16* __restrict__ V, const float* __restrict__ mbias,
    const int* __restrict__ mbflag,
    const float* __restrict__ relk, const float* __restrict__ relv,
    float* __restrict__ O)
{
    extern __shared__ float smem[];
    float* qs = smem;                                     // [128][73] fp32 (log2e-scaled)
    __nv_bfloat16* ksh = (__nv_bfloat16*)(qs + 128 * 73); // 3 x [64][72] bf16
    __nv_bfloat16* vsh = ksh + 3 * KTILEH;                // 3 x [64][72] bf16
    float* rks   = (float*)(vsh + 3 * VTILEH);            // [9][64]
    float* rvs   = rks   + 9 * 64;                        // [9][64]
    float* relb  = rvs   + 9 * 64;                        // [128][12]
    float* pwin  = relb  + 128 * 12;                      // [128][12]
    float* invli = pwin  + 128 * 12;                      // [128]
    float* msksb = invli + 128;                           // 3 x [64] additive bias
    int*   flagss = (int*)(msksb + 3 * 64);               // [16] per-tile mask flags

    const int tid = threadIdx.x;
    const int lane = tid & 31, warp = tid >> 5;
    const int b = blockIdx.z, h = blockIdx.y;
    const int l0 = blockIdx.x * 128;

    const float* qp = Q  + ((size_t)b * CC + h * DD) * LL;
    const __nv_bfloat16* kph = Kk + ((size_t)b * CC + h * DD) * LL;
    const __nv_bfloat16* vph = V + ((size_t)b * CC + h * DD) * LL;
    const float* mbp = mbias + (size_t)b * LL;

    const uint32_t sK = (uint32_t)__cvta_generic_to_shared(ksh);
    const uint32_t sV = (uint32_t)__cvta_generic_to_shared(vsh);
    const uint32_t sM = (uint32_t)__cvta_generic_to_shared(msksb);

    #define AISSUE(ST, T) do { \
        const int _m0 = (T) * 64; \
        _Pragma("unroll") \
        for (int i = 0; i < 2; i++) { \
            int ch = i * 256 + tid; \
            int vd = ch >> 3, vm = (ch & 7) * 8; \
            cpa16(sK + (uint32_t)((ST) * KTILEH + vd * KSTRH + vm) * 2, \
                  kph + (size_t)vd * LL + _m0 + vm); \
            cpa16(sV + (uint32_t)((ST) * VTILEH + vd * VSTRH + vm) * 2, \
                  vph + (size_t)vd * LL + _m0 + vm); \
        } \
        if (tid < 16) cpa16(sM + (uint32_t)((ST) * 64 + tid * 4) * 4, mbp + _m0 + tid * 4); \
        asm volatile("cp.async.commit_group;" ::: "memory"); \
    } while (0)

    AISSUE(0, 0);
    AISSUE(1, 1);

    // ---- stage Q (transpose, scaled by SCALEC*log2e), rel tables, flags ----
    #pragma unroll
    for (int i = 0; i < 8; i++) {
        int d = (tid >> 5) + i * 8;
        int l = (tid & 31) * 4;
        float4 qv = *(const float4*)&qp[(size_t)d * LL + l0 + l];
        qs[(l+0)*73 + d] = qv.x * SCALE2;
        qs[(l+1)*73 + d] = qv.y * SCALE2;
        qs[(l+2)*73 + d] = qv.z * SCALE2;
        qs[(l+3)*73 + d] = qv.w * SCALE2;
    }
    for (int i = tid; i < 9 * 64; i += 256) { rks[i] = relk[i]; rvs[i] = relv[i]; }
    for (int i = tid; i < 128 * 12; i += 256) pwin[i] = 0.f;
    if (tid < 16) flagss[tid] = mbflag[b * 16 + tid];
    __syncthreads();

    // relbias[l][df] = q_log2scaled[l] . rel_k[df]  (fp32, already in log2 domain)
    for (int i = tid; i < 128 * 9; i += 256) {
        int l = i / 9, df = i % 9;
        const float* qq = &qs[l * 73];
        const float* rr = &rks[df * 64];
        float a = 0.f;
        #pragma unroll 16
        for (int d = 0; d < DD; d++) a = fmaf(qq[d], rr[d], a);
        relb[l * 12 + df] = a;
    }

    const int r0 = warp * 16 + (lane >> 2);
    const int r1 = r0 + 8;
    const int lk = lane & 3, lm = lane >> 2;

    // hoist Q as bf16 m16n8k16 A fragments
    uint32_t qf[4][4];
    #pragma unroll
    for (int c = 0; c < 4; c++) {
        int kb = c * 16 + 2 * lk;
        qf[c][0] = packbf2(qs[r0*73 + kb    ], qs[r0*73 + kb + 1]);
        qf[c][1] = packbf2(qs[r1*73 + kb    ], qs[r1*73 + kb + 1]);
        qf[c][2] = packbf2(qs[r0*73 + kb + 8], qs[r0*73 + kb + 9]);
        qf[c][3] = packbf2(qs[r1*73 + kb + 8], qs[r1*73 + kb + 9]);
    }

    // ldmatrix lane addressing
    const uint32_t vBrowBase = (uint32_t)(((lane >> 4) & 1) * 8 + (lane & 7));
    const uint32_t vBcol = (uint32_t)(((lane >> 3) & 1) * 16);
    const uint32_t kBrow = (uint32_t)(((lane >> 3) & 1) * 8 + (lane & 7));
    const uint32_t kBnb  = (uint32_t)(((lane >> 4) & 1) * 8);

    float co[8][4];
    #pragma unroll
    for (int nt = 0; nt < 8; nt++)
        #pragma unroll
        for (int j = 0; j < 4; j++) co[nt][j] = 0.f;
    float li0 = 0.f, li1 = 0.f;

    const int wrow = l0 + warp * 16;

    const int NT = LL / 64;
    for (int t = 0; t < NT; t++) {
        const int m0 = t * 64;
        asm volatile("cp.async.wait_group 1;" ::: "memory");
        __syncthreads();
        if (t + 2 < NT) AISSUE((t + 2) % 3, t + 2);
        else asm volatile("cp.async.commit_group;" ::: "memory");

        const int buf = t % 3;
        const uint32_t kbase = sK + (uint32_t)(buf * KTILEH) * 2;
        const uint32_t vbase = sV + (uint32_t)(buf * VTILEH) * 2;
        const float* msks = msksb + buf * 64;

        const bool haswin = (m0 + 63 >= wrow - WW) && (m0 <= wrow + 15 + WW);
        const bool hasmask = flagss[t] != 0;

        // ---- S' = (Q*log2e) K^T (bf16) ----
        float s[8][4];
        #pragma unroll
        for (int nt = 0; nt < 8; nt++)
            #pragma unroll
            for (int j = 0; j < 4; j++) s[nt][j] = 0.f;

        #pragma unroll
        for (int kk2 = 0; kk2 < 4; kk2++) {
            #pragma unroll
            for (int ntp = 0; ntp < 4; ntp++) {
                uint32_t bk[4];
                ldm_x4_t(bk, kbase + ((uint32_t)(kk2*16) + kBrow) * (KSTRH*2)
                             + ((uint32_t)(ntp*16) + kBnb) * 2);
                mma_bf16(s[2*ntp    ], qf[kk2], bk);
                mma_bf16(s[2*ntp + 1], qf[kk2], bk + 2);
            }
        }

        // ---- rel_k bias (window tiles only) + mask bias (masked tiles only) ----
        const int gl0 = l0 + r0, gl1 = l0 + r1;
        if (haswin) {
            #pragma unroll
            for (int nt = 0; nt < 8; nt++) {
                #pragma unroll
                for (int j = 0; j < 2; j++) {
                    int gm = m0 + nt*8 + 2*lk + j;
                    int df0 = gm - gl0;
                    if (df0 >= -WW && df0 <= WW) s[nt][j] += relb[r0*12 + df0 + WW];
                    int df1 = gm - gl1;
                    if (df1 >= -WW && df1 <= WW) s[nt][2+j] += relb[r1*12 + df1 + WW];
                }
            }
        }
        if (hasmask) {
            #pragma unroll
            for (int nt = 0; nt < 8; nt++) {
                #pragma unroll
                for (int j = 0; j < 2; j++) {
                    float mb = msks[nt*8 + 2*lk + j];
                    s[nt][j] += mb;
                    s[nt][2+j] += mb;
                }
            }
        }

        // ---- no-max softmax in log2 domain: p = 2^{s'} ----
        #pragma unroll
        for (int nt = 0; nt < 8; nt++) {
            s[nt][0] = ex2(s[nt][0]); s[nt][1] = ex2(s[nt][1]);
            s[nt][2] = ex2(s[nt][2]); s[nt][3] = ex2(s[nt][3]);
            li0 += s[nt][0] + s[nt][1];
            li1 += s[nt][2] + s[nt][3];
        }

        // record window probs
        if (haswin) {
            #pragma unroll
            for (int nt = 0; nt < 8; nt++) {
                #pragma unroll
                for (int j = 0; j < 2; j++) {
                    int gm = m0 + nt*8 + 2*lk + j;
                    int df0 = gm - gl0;
                    if (df0 >= -WW && df0 <= WW) pwin[r0*12 + df0 + WW] = s[nt][j];
                    int df1 = gm - gl1;
                    if (df1 >= -WW && df1 <= WW) pwin[r1*12 + df1 + WW] = s[nt][2+j];
                }
            }
        }

        // ---- O += P V : A-fragments packed directly from S registers ----
        #pragma unroll
        for (int kk2 = 0; kk2 < 4; kk2++) {
            uint32_t a[4];
            a[0] = packbf2(s[2*kk2  ][0], s[2*kk2  ][1]);
            a[1] = packbf2(s[2*kk2  ][2], s[2*kk2  ][3]);
            a[2] = packbf2(s[2*kk2+1][0], s[2*kk2+1][1]);
            a[3] = packbf2(s[2*kk2+1][2], s[2*kk2+1][3]);
            #pragma unroll
            for (int ntp = 0; ntp < 4; ntp++) {
                uint32_t bv[4];
                uint32_t vrow = (uint32_t)(2*ntp*8) + vBrowBase;
                ldm_x4(bv, vbase + vrow * (VSTRH*2) + (uint32_t)(kk2*32) + vBcol);
                mma_bf16(co[2*ntp    ], a, bv);
                mma_bf16(co[2*ntp + 1], a, bv + 2);
            }
        }
    }
    #undef AISSUE

    // ---- reduce li across the 4 lanes of each row group (once) ----
    li0 += __shfl_xor_sync(0xffffffffu, li0, 1);
    li0 += __shfl_xor_sync(0xffffffffu, li0, 2);
    li1 += __shfl_xor_sync(0xffffffffu, li1, 1);
    li1 += __shfl_xor_sync(0xffffffffu, li1, 2);

    // ---- epilogue ----
    __syncthreads();
    float* outb = (float*)ksh;
    float inv0 = 1.0f / fmaxf(li0, 1e-20f);
    float inv1 = 1.0f / fmaxf(li1, 1e-20f);
    if (lk == 0) { invli[r0] = inv0; invli[r1] = inv1; }
    #pragma unroll
    for (int nt = 0; nt < 8; nt++) {
        int c = nt*8 + 2*lk;
        outb[r0*73 + c    ] = co[nt][0] * inv0;
        outb[r0*73 + c + 1] = co[nt][1] * inv0;
        outb[r1*73 + c    ] = co[nt][2] * inv1;
        outb[r1*73 + c + 1] = co[nt][3] * inv1;
    }
    __syncthreads();

    float* op = O + ((size_t)b * CC + h * DD) * LL;
    #pragma unroll
    for (int i = 0; i < 32; i++) {
        int idx = i * 256 + tid;
        int l = idx & 127;
        int d = idx >> 7;
        float r = 0.f;
        #pragma unroll
        for (int df = 0; df < 9; df++) r = fmaf(pwin[l*12 + df], rvs[df*64 + d], r);
        op[(size_t)d * LL + l0 + l] = rntf(outb[l*73 + d] + invli[l] * r);
    }
}

// ---------- fused residual add (2 deltas) + LayerNorm, smem-cached ---------------
__global__ void add_ln_kernel(const float* __restrict__ X, const float* __restrict__ D0,
                              const float* __restrict__ D1,
                              const float* __restrict__ gam, const float* __restrict__ bet,
                              float* __restrict__ Yo, float* __restrict__ Yr,
                              float* __restrict__ Yext, const float* __restrict__ fm)
{
    __shared__ float vbuf[CC][17];
    __shared__ float sm[16][17], sq[16][17];
    int b = blockIdx.y;
    int l = blockIdx.x * 16 + threadIdx.x;
    int cg = threadIdx.y;
    int lx = threadIdx.x;
    const size_t base = (size_t)b * CC * LL + l;

    float s = 0.f, s2 = 0.f;
    for (int c = cg; c < CC; c += 16) {
        float v = X[base + (size_t)c * LL] + D0[base + (size_t)c * LL] + D1[base + (size_t)c * LL];
        vbuf[c][lx] = v;
        s += v; s2 += v * v;
    }
    sm[cg][lx] = s; sq[cg][lx] = s2;
    __syncthreads();
    float ts = 0.f, ts2 = 0.f;
    #pragma unroll
    for (int i = 0; i < 16; i++) { ts += sm[i][lx]; ts2 += sq[i][lx]; }
    float mean = ts * (1.0f / CC);
    float var  = ts2 * (1.0f / CC) - mean * mean;
    float rstd = rsqrtf(var + EPSC);
    float mval = Yext ? fm[(size_t)b * LL + l] : 0.f;
    for (int c = cg; c < CC; c += 16) {
        float v = vbuf[c][lx];
        float y = (v - mean) * rstd * gam[c] + bet[c];
        Yo[base + (size_t)c * LL] = y;
        Yr[base + (size_t)c * LL] = rntf(y);
        if (Yext) Yext[base + (size_t)c * LL] = y * mval;
    }
}

// ---------------- host orchestration -------------------------------------------
extern "C" void kernel_launch(void* const* d_in, const int* in_sizes, int n_in,
                              void* d_out, int out_size)
{
    const float* x    = (const float*)d_in[0];
    const float* mask = (const float*)d_in[1];
    const float* wq = (const float*)d_in[2];  const float* bq = (const float*)d_in[3];
    const float* wk = (const float*)d_in[4];  const float* bk = (const float*)d_in[5];
    const float* wv = (const float*)d_in[6];  const float* bv = (const float*)d_in[7];
    const float* wo = (const float*)d_in[8];  const float* bo = (const float*)d_in[9];
    const float* relk = (const float*)d_in[10];
    const float* relv = (const float*)d_in[11];
    const float* ln1g = (const float*)d_in[12]; const float* ln1b = (const float*)d_in[13];
    const float* w1 = (const float*)d_in[14]; const float* b1 = (const float*)d_in[15];
    const float* w2 = (const float*)d_in[16]; const float* b2 = (const float*)d_in[17];
    const float* ln2g = (const float*)d_in[18]; const float* ln2b = (const float*)d_in[19];

    float *px, *pxr, *pq, *pk, *pv, *pa, *pt, *ph, *pz, *pmb;
    int *pmbf;
    float *rwq, *rwk, *rwv, *rwo, *rw1, *rw2;
    cudaGetSymbolAddress((void**)&px, g_x);
    cudaGetSymbolAddress((void**)&pxr, g_xr);
    cudaGetSymbolAddress((void**)&pq, g_q);
    cudaGetSymbolAddress((void**)&pk, g_k);
    cudaGetSymbolAddress((void**)&pv, g_v);
    cudaGetSymbolAddress((void**)&pa, g_a);
    cudaGetSymbolAddress((void**)&pt, g_t);
    cudaGetSymbolAddress((void**)&ph, g_h);
    cudaGetSymbolAddress((void**)&pz, g_zero);
    cudaGetSymbolAddress((void**)&pmb, g_mb);
    cudaGetSymbolAddress((void**)&pmbf, g_mbflag);
    cudaGetSymbolAddress((void**)&rwq, g_rwq);
    cudaGetSymbolAddress((void**)&rwk, g_rwk);
    cudaGetSymbolAddress((void**)&rwv, g_rwv);
    cudaGetSymbolAddress((void**)&rwo, g_rwo);
    cudaGetSymbolAddress((void**)&rw1, g_rw1);
    cudaGetSymbolAddress((void**)&rw2, g_rw2);
    float* pt2 = pk;   // split-K partial #2

    const size_t attn_smem = (size_t)(128*73) * 4
                           + (size_t)(3*KTILEH + 3*VTILEH) * 2
                           + (size_t)(9*64*2 + 128*12*2 + 128 + 3*64) * 4
                           + 16 * 4;
    cudaFuncSetAttribute(attn_tc_kernel, cudaFuncAttributeMaxDynamicSharedMemorySize, (int)attn_smem);
    const size_t gemm_smem = (size_t)(NSTG * STG_A + NSTG * STG_B) * sizeof(float);
    cudaFuncSetAttribute(gemm_tc_kernel, cudaFuncAttributeMaxDynamicSharedMemorySize, (int)gemm_smem);

    const size_t totalF4 = (size_t)4 * NW4 + 2 * NF4;
    roundcpy6_kernel<<<(unsigned)(totalF4 / 256), 256>>>(
        (const float4*)wq, (const float4*)wk, (const float4*)wv, (const float4*)wo,
        (const float4*)w1, (const float4*)w2,
        (float4*)rwq, (float4*)rwk, (float4*)rwv, (float4*)rwo,
        (float4*)rw1, (float4*)rw2);

    const int nElem = BB * CC * LL;
    maskmul_kernel<<<nElem / 256, 256>>>(x, mask, px, pxr);
    maskbias_kernel<<<BB * LL / 64, 64>>>(mask, pmb, pmbf);

    dim3 gQKV(LL / 128, CC / 128, 3 * BB);
    dim3 gSK(LL / 128, CC / 128, 2 * BB);
    dim3 gF1(LL / 128, FCC / 128, BB);
    dim3 gAttn(LL / 128, HH, BB);
    dim3 gLN(LL / 16, BB);
    dim3 bLN(16, 16);

    for (int i = 0; i < NLL; i++) {
        const float* Wq = rwq + (size_t)i * CC * CC;
        const float* Wk = rwk + (size_t)i * CC * CC;
        const float* Wv = rwv + (size_t)i * CC * CC;
        const float* Wo = rwo + (size_t)i * CC * CC;
        const float* W1 = rw1 + (size_t)i * FCC * CC;
        const float* W2 = rw2 + (size_t)i * CC * FCC;
        const bool last = (i == NLL - 1);

        gemm_tc_kernel<<<gQKV, 256, gemm_smem>>>(Wq, Wk, Wv, bq + i*CC, bk + i*CC, bv + i*CC,
                                                 pxr, mask, pq, pk, pv, CC, LL, CC, 16 | 32);

        attn_tc_kernel<<<gAttn, 256, attn_smem>>>(pq, (const __nv_bfloat16*)pk,
                                                  (const __nv_bfloat16*)pv, pmb, pmbf,
                                                  relk + (size_t)i * 9 * DD,
                                                  relv + (size_t)i * 9 * DD, pa);

        gemm_tc_kernel<<<gSK, 256, gemm_smem>>>(Wo, Wo, Wo, bo + i*CC, pz, pz,
                                                pa, mask, pt, pt2, pt2, CC, LL, CC, 8);
        add_ln_kernel<<<gLN, bLN>>>(px, pt, pt2, ln1g + i*CC, ln1b + i*CC,
                                    px, pxr, nullptr, mask);

        gemm_tc_kernel<<<gF1, 256, gemm_smem>>>(W1, W1, W1, b1 + i*FCC, b1 + i*FCC, b1 + i*FCC,
                                                pxr, mask, ph, ph, ph, FCC, LL, CC, 2 | 4 | 16);
        gemm_tc_kernel<<<gSK, 256, gemm_smem>>>(W2, W2, W2, b2 + i*CC, pz, pz,
                                                ph, mask, pt, pt2, pt2, CC, LL, FCC, 8 | 4);
        add_ln_kernel<<<gLN, bLN>>>(px, pt, pt2, ln2g + i*CC, ln2b + i*CC,
                                    px, pxr, last ? (float*)d_out : nullptr, mask);
    }
}